// round 5
// baseline (speedup 1.0000x reference)
#include <cuda_runtime.h>
#include <cuda_bf16.h>

#define B_  8
#define H_  8
#define N_  512
#define K_  16
#define BN  (B_*N_)          // 4096
#define NN  (N_*N_)          // 262144
#define M_TAYLOR 24

__device__ float g_A[BN * 256];   // per-(b,n) algebra element A = phi . G, row-major 16x16
__device__ float g_V[BN * K_];    // v = exp(-A) mu

// ---------------------------------------------------------------------------
// Warp-collective: y = exp(A) x for a 16x16 A.
// Lane l owns row r = l&15 of A. x_own = component r of x.
// Horner: y <- x + (A y)/k, k = M..1. y kept replicated in all lanes.
// ---------------------------------------------------------------------------
__device__ __forceinline__ float exp_apply(const float Ar[16], float x_own) {
    float x[16], y[16];
    #pragma unroll
    for (int c = 0; c < 16; ++c) {
        x[c] = __shfl_sync(0xffffffffu, x_own, c);
        y[c] = x[c];
    }
    float y_own = x_own;
    #pragma unroll
    for (int k = M_TAYLOR; k >= 1; --k) {
        float z0 = 0.0f, z1 = 0.0f;
        #pragma unroll
        for (int c = 0; c < 16; c += 2) {
            z0 += Ar[c]     * y[c];
            z1 += Ar[c + 1] * y[c + 1];
        }
        float zk = (z0 + z1) * (1.0f / (float)k);
        y_own = x_own + zk;
        #pragma unroll
        for (int c = 0; c < 16; ++c)
            y[c] = x[c] + __shfl_sync(0xffffffffu, zk, c);
    }
    return y_own;
}

// ---------------------------------------------------------------------------
// Kernel 1: per (b,n): build A = sum_g phi_g G_g (store), v = exp(-A) mu (store).
// ---------------------------------------------------------------------------
__global__ __launch_bounds__(256)
void prep_kernel(const float* __restrict__ mu,
                 const float* __restrict__ phi,
                 const float* __restrict__ gen) {
    int w = threadIdx.x >> 5, lane = threadIdx.x & 31, r = lane & 15;
    int bn = blockIdx.x * 8 + w;

    float p0 = phi[bn * 3 + 0], p1 = phi[bn * 3 + 1], p2 = phi[bn * 3 + 2];

    float Ar[16];
    const float4* g4 = (const float4*)gen;
    #pragma unroll
    for (int q = 0; q < 4; ++q) {
        float4 a = g4[(0 * 256 + r * 16) / 4 + q];
        float4 b = g4[(1 * 256 + r * 16) / 4 + q];
        float4 c = g4[(2 * 256 + r * 16) / 4 + q];
        Ar[4 * q + 0] = p0 * a.x + p1 * b.x + p2 * c.x;
        Ar[4 * q + 1] = p0 * a.y + p1 * b.y + p2 * c.y;
        Ar[4 * q + 2] = p0 * a.z + p1 * b.z + p2 * c.z;
        Ar[4 * q + 3] = p0 * a.w + p1 * b.w + p2 * c.w;
    }
    if (lane < 16) {
        float4* A4 = (float4*)(g_A + (size_t)bn * 256 + r * 16);
        #pragma unroll
        for (int q = 0; q < 4; ++q)
            A4[q] = make_float4(Ar[4*q], Ar[4*q+1], Ar[4*q+2], Ar[4*q+3]);
    }

    float nAr[16];
    #pragma unroll
    for (int c = 0; c < 16; ++c) nAr[c] = -Ar[c];

    float x_own = mu[bn * 16 + r];
    float v = exp_apply(nAr, x_own);
    if (lane < 16) g_V[bn * 16 + lane] = v;
}

// ---------------------------------------------------------------------------
// Kernel 2: warp-per-row main pass. Block = 8 warps = 8 rows of one batch.
// V[b] cached in smem stride-20 (conflict-free float4 LDS).
// 4 blocks/SM resident -> grid fits in ONE wave, 32 warps/SM for MLP.
// ---------------------------------------------------------------------------
__global__ __launch_bounds__(256, 4)
void vffn_main_kernel(const float* __restrict__ beta,
                      const float* __restrict__ mu,
                      const float* __restrict__ mu_prior,
                      const float* __restrict__ lr_ptr,
                      float* __restrict__ out) {
    __shared__ float Vs[N_ * 20];
    __shared__ float qs[N_];
    __shared__ float scratch[8][16];

    int t = threadIdx.x, lane = t & 31, w = t >> 5, r = lane & 15;
    int b = blockIdx.x >> 6;                 // 64 blocks per batch
    int i = ((blockIdx.x & 63) << 3) + w;    // this warp's row
    int bn = b * N_ + i;
    float lr = *lr_ptr;

    // Stage V[b] into padded smem (stride 20 floats; float4-aligned)
    const float4* V4 = (const float4*)(g_V + (size_t)b * N_ * K_);
    for (int idx = t; idx < N_ * 4; idx += 256) {
        int j = idx >> 2, q = idx & 3;
        ((float4*)(Vs + j * 20))[q] = V4[j * 4 + q];
    }
    __syncthreads();
    for (int j = t; j < N_; j += 256) {
        float q = 0.0f;
        #pragma unroll
        for (int k = 0; k < 16; ++k) { float v = Vs[j * 20 + k]; q += v * v; }
        qs[j] = q;
    }
    __syncthreads();

    // vi (broadcast LDS) and qi
    float vi[16];
    #pragma unroll
    for (int q = 0; q < 4; ++q) {
        float4 v4 = ((const float4*)(Vs + i * 20))[q];
        vi[4*q] = v4.x; vi[4*q+1] = v4.y; vi[4*q+2] = v4.z; vi[4*q+3] = v4.w;
    }
    float qi = qs[i];

    float S0 = 0.0f, sac = 0.0f;
    float Sv[16], Tv[16];
    #pragma unroll
    for (int k = 0; k < 16; ++k) { Sv[k] = 0.0f; Tv[k] = 0.0f; }

    const float* bb = beta + (size_t)b * H_ * NN + (size_t)i * N_;

    #pragma unroll 4
    for (int jj = 0; jj < 16; ++jj) {
        int j = lane + jj * 32;
        // 8 head loads, streaming (read-once data: don't pollute L2)
        float b0 = __ldcs(bb + 0*NN + j), b1 = __ldcs(bb + 1*NN + j);
        float b2 = __ldcs(bb + 2*NN + j), b3 = __ldcs(bb + 3*NN + j);
        float b4 = __ldcs(bb + 4*NN + j), b5 = __ldcs(bb + 5*NN + j);
        float b6 = __ldcs(bb + 6*NN + j), b7 = __ldcs(bb + 7*NN + j);
        float cb = (((b0 + b1) + (b2 + b3)) + ((b4 + b5) + (b6 + b7))) * 0.125f;

        float vj[16];
        #pragma unroll
        for (int q = 0; q < 4; ++q) {
            float4 u = ((const float4*)(Vs + j * 20))[q];
            vj[4*q] = u.x; vj[4*q+1] = u.y; vj[4*q+2] = u.z; vj[4*q+3] = u.w;
        }
        float d0 = 0.0f, d1 = 0.0f;
        #pragma unroll
        for (int k = 0; k < 16; k += 2) { d0 += vi[k]*vj[k]; d1 += vi[k+1]*vj[k+1]; }
        float kl  = 0.5f * (qi + qs[j]) - (d0 + d1);   // / TAU = 1
        float wgt = cb * kl;
        S0  += cb;
        sac += wgt;
        #pragma unroll
        for (int k = 0; k < 16; ++k) {
            Sv[k] += cb  * vj[k];
            Tv[k] += wgt * vj[k];
        }
    }

    // Butterfly all-reduce of the 34 partials across the warp
    #pragma unroll
    for (int off = 16; off > 0; off >>= 1) {
        S0  += __shfl_xor_sync(0xffffffffu, S0,  off);
        sac += __shfl_xor_sync(0xffffffffu, sac, off);
        #pragma unroll
        for (int k = 0; k < 16; ++k) {
            Sv[k] += __shfl_xor_sync(0xffffffffu, Sv[k], off);
            Tv[k] += __shfl_xor_sync(0xffffffffu, Tv[k], off);
        }
    }

    // rv (pre-rotation gradient), replicated in all lanes
    float rv[16];
    #pragma unroll
    for (int k = 0; k < 16; ++k) {
        float r1 = S0 * vi[k] - Sv[k];                                // grad1 (tau=1)
        float r2 = sac * (1.0f - S0) * vi[k] + sac * Sv[k] - Tv[k];   // grad2 (tau*kappa=1)
        rv[k] = r1 + r2;
    }
    // Extract component r into rv_own via per-warp smem staging
    if (lane == 0) {
        #pragma unroll
        for (int c = 0; c < 16; ++c) scratch[w][c] = rv[c];
    }
    __syncwarp();
    float rv_own = scratch[w][r];

    // Load A row r, apply rotation grad = exp(A) rv
    float Ar[16];
    const float4* A4 = (const float4*)(g_A + (size_t)bn * 256 + r * 16);
    #pragma unroll
    for (int q = 0; q < 4; ++q) {
        float4 a = A4[q];
        Ar[4*q] = a.x; Ar[4*q+1] = a.y; Ar[4*q+2] = a.z; Ar[4*q+3] = a.w;
    }
    float grad = exp_apply(Ar, rv_own);

    if (lane < 16) {
        float m  = mu[bn * 16 + lane];
        float mp = mu_prior[bn * 16 + lane];
        out[bn * 16 + lane] = m - lr * (0.001f * (m - mp) + grad);
    }
}

// ---------------------------------------------------------------------------
extern "C" void kernel_launch(void* const* d_in, const int* in_sizes, int n_in,
                              void* d_out, int out_size) {
    const float* mu       = (const float*)d_in[0];
    const float* beta     = (const float*)d_in[1];
    const float* mu_prior = (const float*)d_in[2];
    const float* phi      = (const float*)d_in[3];
    const float* gen      = (const float*)d_in[4];
    const float* lr       = (const float*)d_in[5];
    float* out = (float*)d_out;

    prep_kernel<<<BN / 8, 256>>>(mu, phi, gen);
    vffn_main_kernel<<<BN / 8, 256>>>(beta, mu, mu_prior, lr, out);
}

// round 7
// speedup vs baseline: 1.5021x; 1.5021x over previous
#include <cuda_runtime.h>
#include <cuda_bf16.h>

#define B_  8
#define H_  8
#define N_  512
#define K_  16
#define BN  (B_*N_)          // 4096
#define NN  (N_*N_)          // 262144
#define M_TAYLOR 24

__device__ float g_A[BN * 256];     // per-(b,n) algebra element A, row-major 16x16
__device__ float g_V[BN * K_];      // v = exp(-A) mu
__device__ float g_bavg[B_ * NN];   // head-averaged beta (8 MB)

// ---------------------------------------------------------------------------
// Warp-collective: y = exp(A) x for a 16x16 A.
// Lane l owns row r = l&15 of A. x_own = component r of x.
// ---------------------------------------------------------------------------
__device__ __forceinline__ float exp_apply(const float Ar[16], float x_own) {
    float x[16], y[16];
    #pragma unroll
    for (int c = 0; c < 16; ++c) {
        x[c] = __shfl_sync(0xffffffffu, x_own, c);
        y[c] = x[c];
    }
    float y_own = x_own;
    #pragma unroll
    for (int k = M_TAYLOR; k >= 1; --k) {
        float z0 = 0.0f, z1 = 0.0f;
        #pragma unroll
        for (int c = 0; c < 16; c += 2) {
            z0 += Ar[c]     * y[c];
            z1 += Ar[c + 1] * y[c + 1];
        }
        float zk = (z0 + z1) * (1.0f / (float)k);
        y_own = x_own + zk;
        #pragma unroll
        for (int c = 0; c < 16; ++c)
            y[c] = x[c] + __shfl_sync(0xffffffffu, zk, c);
    }
    return y_own;
}

// ---------------------------------------------------------------------------
// Kernel 0: pure streaming head-average. One float4 of (b,i,j) per thread,
// 8 independent LDG.128 in flight per thread. 64 MB read / 8 MB write.
// ---------------------------------------------------------------------------
__global__ __launch_bounds__(256)
void havg_kernel(const float* __restrict__ beta) {
    int m4 = blockIdx.x * 256 + threadIdx.x;   // float4 index, B_*NN/4 total
    int b  = m4 >> 16;                          // / (NN/4 = 65536)
    int r4 = m4 & 65535;
    const float4* src = (const float4*)beta + (size_t)b * (H_ * NN / 4) + r4;

    float4 v0 = src[0 * (NN/4)], v1 = src[1 * (NN/4)];
    float4 v2 = src[2 * (NN/4)], v3 = src[3 * (NN/4)];
    float4 v4 = src[4 * (NN/4)], v5 = src[5 * (NN/4)];
    float4 v6 = src[6 * (NN/4)], v7 = src[7 * (NN/4)];

    float4 s;
    s.x = (((v0.x + v1.x) + (v2.x + v3.x)) + ((v4.x + v5.x) + (v6.x + v7.x))) * 0.125f;
    s.y = (((v0.y + v1.y) + (v2.y + v3.y)) + ((v4.y + v5.y) + (v6.y + v7.y))) * 0.125f;
    s.z = (((v0.z + v1.z) + (v2.z + v3.z)) + ((v4.z + v5.z) + (v6.z + v7.z))) * 0.125f;
    s.w = (((v0.w + v1.w) + (v2.w + v3.w)) + ((v4.w + v5.w) + (v6.w + v7.w))) * 0.125f;

    ((float4*)g_bavg)[m4] = s;
}

// ---------------------------------------------------------------------------
// Kernel 1: per (b,n): build A = sum_g phi_g G_g (store), v = exp(-A) mu.
// ---------------------------------------------------------------------------
__global__ __launch_bounds__(256)
void prep_kernel(const float* __restrict__ mu,
                 const float* __restrict__ phi,
                 const float* __restrict__ gen) {
    int w = threadIdx.x >> 5, lane = threadIdx.x & 31, r = lane & 15;
    int bn = blockIdx.x * 8 + w;

    float p0 = phi[bn * 3 + 0], p1 = phi[bn * 3 + 1], p2 = phi[bn * 3 + 2];

    float Ar[16];
    const float4* g4 = (const float4*)gen;
    #pragma unroll
    for (int q = 0; q < 4; ++q) {
        float4 a = g4[(0 * 256 + r * 16) / 4 + q];
        float4 b = g4[(1 * 256 + r * 16) / 4 + q];
        float4 c = g4[(2 * 256 + r * 16) / 4 + q];
        Ar[4 * q + 0] = p0 * a.x + p1 * b.x + p2 * c.x;
        Ar[4 * q + 1] = p0 * a.y + p1 * b.y + p2 * c.y;
        Ar[4 * q + 2] = p0 * a.z + p1 * b.z + p2 * c.z;
        Ar[4 * q + 3] = p0 * a.w + p1 * b.w + p2 * c.w;
    }
    if (lane < 16) {
        float4* A4 = (float4*)(g_A + (size_t)bn * 256 + r * 16);
        #pragma unroll
        for (int q = 0; q < 4; ++q)
            A4[q] = make_float4(Ar[4*q], Ar[4*q+1], Ar[4*q+2], Ar[4*q+3]);
    }

    float nAr[16];
    #pragma unroll
    for (int c = 0; c < 16; ++c) nAr[c] = -Ar[c];

    float x_own = mu[bn * 16 + r];
    float v = exp_apply(nAr, x_own);
    if (lane < 16) g_V[bn * 16 + lane] = v;
}

// ---------------------------------------------------------------------------
// Kernel 2: warp-per-row main pass over the (mostly L2-resident) beta_avg.
// Block = 8 warps = 8 rows of one batch. V[b] in smem stride-20 (conflict-free).
// NO min-blocks clause: let regs stay ~124 (no spills; R5 lesson).
// ---------------------------------------------------------------------------
__global__ __launch_bounds__(256)
void vffn_main_kernel(const float* __restrict__ mu,
                      const float* __restrict__ mu_prior,
                      const float* __restrict__ lr_ptr,
                      float* __restrict__ out) {
    __shared__ float Vs[N_ * 20];
    __shared__ float qs[N_];
    __shared__ float scratch[8][16];

    int t = threadIdx.x, lane = t & 31, w = t >> 5, r = lane & 15;
    int b = blockIdx.x >> 6;                 // 64 blocks per batch
    int i = ((blockIdx.x & 63) << 3) + w;    // this warp's row
    int bn = b * N_ + i;
    float lr = *lr_ptr;

    // Stage V[b] into padded smem (stride 20 floats; float4-aligned)
    const float4* V4 = (const float4*)(g_V + (size_t)b * N_ * K_);
    for (int idx = t; idx < N_ * 4; idx += 256) {
        int j = idx >> 2, q = idx & 3;
        ((float4*)(Vs + j * 20))[q] = V4[j * 4 + q];
    }
    __syncthreads();
    for (int j = t; j < N_; j += 256) {
        float q = 0.0f;
        #pragma unroll
        for (int k = 0; k < 16; ++k) { float v = Vs[j * 20 + k]; q += v * v; }
        qs[j] = q;
    }
    __syncthreads();

    float vi[16];
    #pragma unroll
    for (int q = 0; q < 4; ++q) {
        float4 v4 = ((const float4*)(Vs + i * 20))[q];
        vi[4*q] = v4.x; vi[4*q+1] = v4.y; vi[4*q+2] = v4.z; vi[4*q+3] = v4.w;
    }
    float qi = qs[i];

    float S0 = 0.0f, sac = 0.0f;
    float Sv[16], Tv[16];
    #pragma unroll
    for (int k = 0; k < 16; ++k) { Sv[k] = 0.0f; Tv[k] = 0.0f; }

    // This warp's beta_avg row: 512 floats = 4 float4 per lane
    const float4* ba4 = (const float4*)(g_bavg + (size_t)b * NN + (size_t)i * N_);
    float4 bv[4];
    #pragma unroll
    for (int c = 0; c < 4; ++c) bv[c] = ba4[lane + 32 * c];

    #pragma unroll
    for (int c = 0; c < 4; ++c) {
        float cbq[4] = {bv[c].x, bv[c].y, bv[c].z, bv[c].w};
        #pragma unroll
        for (int q = 0; q < 4; ++q) {
            int j = 128 * c + 4 * lane + q;
            float cb = cbq[q];

            float vj[16];
            #pragma unroll
            for (int p = 0; p < 4; ++p) {
                float4 u = ((const float4*)(Vs + j * 20))[p];
                vj[4*p] = u.x; vj[4*p+1] = u.y; vj[4*p+2] = u.z; vj[4*p+3] = u.w;
            }
            float d0 = 0.0f, d1 = 0.0f;
            #pragma unroll
            for (int k = 0; k < 16; k += 2) { d0 += vi[k]*vj[k]; d1 += vi[k+1]*vj[k+1]; }
            float kl  = 0.5f * (qi + qs[j]) - (d0 + d1);   // / TAU = 1
            float wgt = cb * kl;
            S0  += cb;
            sac += wgt;
            #pragma unroll
            for (int k = 0; k < 16; ++k) {
                Sv[k] += cb  * vj[k];
                Tv[k] += wgt * vj[k];
            }
        }
    }

    // Butterfly all-reduce of the 34 partials across the warp
    #pragma unroll
    for (int off = 16; off > 0; off >>= 1) {
        S0  += __shfl_xor_sync(0xffffffffu, S0,  off);
        sac += __shfl_xor_sync(0xffffffffu, sac, off);
        #pragma unroll
        for (int k = 0; k < 16; ++k) {
            Sv[k] += __shfl_xor_sync(0xffffffffu, Sv[k], off);
            Tv[k] += __shfl_xor_sync(0xffffffffu, Tv[k], off);
        }
    }

    // rv (pre-rotation gradient), replicated in all lanes
    float rv[16];
    #pragma unroll
    for (int k = 0; k < 16; ++k) {
        float r1 = S0 * vi[k] - Sv[k];                                // grad1 (tau=1)
        float r2 = sac * (1.0f - S0) * vi[k] + sac * Sv[k] - Tv[k];   // grad2 (tau*kappa=1)
        rv[k] = r1 + r2;
    }
    if (lane == 0) {
        #pragma unroll
        for (int c = 0; c < 16; ++c) scratch[w][c] = rv[c];
    }
    __syncwarp();
    float rv_own = scratch[w][r];

    // Rotation grad = exp(A) rv
    float Ar[16];
    const float4* A4 = (const float4*)(g_A + (size_t)bn * 256 + r * 16);
    #pragma unroll
    for (int q = 0; q < 4; ++q) {
        float4 a = A4[q];
        Ar[4*q] = a.x; Ar[4*q+1] = a.y; Ar[4*q+2] = a.z; Ar[4*q+3] = a.w;
    }
    float grad = exp_apply(Ar, rv_own);

    if (lane < 16) {
        float m  = mu[bn * 16 + lane];
        float mp = mu_prior[bn * 16 + lane];
        out[bn * 16 + lane] = m - lr * (0.001f * (m - mp) + grad);
    }
}

// ---------------------------------------------------------------------------
extern "C" void kernel_launch(void* const* d_in, const int* in_sizes, int n_in,
                              void* d_out, int out_size) {
    const float* mu       = (const float*)d_in[0];
    const float* beta     = (const float*)d_in[1];
    const float* mu_prior = (const float*)d_in[2];
    const float* phi      = (const float*)d_in[3];
    const float* gen      = (const float*)d_in[4];
    const float* lr       = (const float*)d_in[5];
    float* out = (float*)d_out;

    havg_kernel<<<(B_ * NN / 4) / 256, 256>>>(beta);
    prep_kernel<<<BN / 8, 256>>>(mu, phi, gen);
    vffn_main_kernel<<<BN / 8, 256>>>(mu, mu_prior, lr, out);
}

// round 8
// speedup vs baseline: 1.8427x; 1.2268x over previous
#include <cuda_runtime.h>
#include <cuda_bf16.h>

#define B_  8
#define H_  8
#define N_  512
#define K_  16
#define BN  (B_*N_)          // 4096
#define NN  (N_*N_)          // 262144
#define M_TAYLOR 24

__device__ float g_A[BN * 256];     // per-(b,n) algebra element A, row-major 16x16
__device__ float g_V[BN * K_];      // v = exp(-A) mu
__device__ float g_bavg[B_ * NN];   // head-averaged beta (8 MB)

// ---------------------------------------------------------------------------
// Warp-collective: y = exp(A) x for a 16x16 A.
// Lane l owns row r = l&15 of A. x_own = component r of x.
// ---------------------------------------------------------------------------
__device__ __forceinline__ float exp_apply(const float Ar[16], float x_own) {
    float x[16], y[16];
    #pragma unroll
    for (int c = 0; c < 16; ++c) {
        x[c] = __shfl_sync(0xffffffffu, x_own, c);
        y[c] = x[c];
    }
    float y_own = x_own;
    #pragma unroll
    for (int k = M_TAYLOR; k >= 1; --k) {
        float z0 = 0.0f, z1 = 0.0f;
        #pragma unroll
        for (int c = 0; c < 16; c += 2) {
            z0 += Ar[c]     * y[c];
            z1 += Ar[c + 1] * y[c + 1];
        }
        float zk = (z0 + z1) * (1.0f / (float)k);
        y_own = x_own + zk;
        #pragma unroll
        for (int c = 0; c < 16; ++c)
            y[c] = x[c] + __shfl_sync(0xffffffffu, zk, c);
    }
    return y_own;
}

// ---------------------------------------------------------------------------
// Kernel 0: pure streaming head-average. One float4 of (b,i,j) per thread,
// 8 independent LDG.128 in flight per thread. 64 MB read / 8 MB write.
// ---------------------------------------------------------------------------
__global__ __launch_bounds__(256)
void havg_kernel(const float* __restrict__ beta) {
    int m4 = blockIdx.x * 256 + threadIdx.x;   // float4 index, B_*NN/4 total
    int b  = m4 >> 16;                          // / (NN/4 = 65536)
    int r4 = m4 & 65535;
    const float4* src = (const float4*)beta + (size_t)b * (H_ * NN / 4) + r4;

    float4 v0 = src[0 * (NN/4)], v1 = src[1 * (NN/4)];
    float4 v2 = src[2 * (NN/4)], v3 = src[3 * (NN/4)];
    float4 v4 = src[4 * (NN/4)], v5 = src[5 * (NN/4)];
    float4 v6 = src[6 * (NN/4)], v7 = src[7 * (NN/4)];

    float4 s;
    s.x = (((v0.x + v1.x) + (v2.x + v3.x)) + ((v4.x + v5.x) + (v6.x + v7.x))) * 0.125f;
    s.y = (((v0.y + v1.y) + (v2.y + v3.y)) + ((v4.y + v5.y) + (v6.y + v7.y))) * 0.125f;
    s.z = (((v0.z + v1.z) + (v2.z + v3.z)) + ((v4.z + v5.z) + (v6.z + v7.z))) * 0.125f;
    s.w = (((v0.w + v1.w) + (v2.w + v3.w)) + ((v4.w + v5.w) + (v6.w + v7.w))) * 0.125f;

    ((float4*)g_bavg)[m4] = s;
}

// ---------------------------------------------------------------------------
// Kernel 1: per (b,n): build A = sum_g phi_g G_g (store), v = exp(-A) mu.
// ---------------------------------------------------------------------------
__global__ __launch_bounds__(256)
void prep_kernel(const float* __restrict__ mu,
                 const float* __restrict__ phi,
                 const float* __restrict__ gen) {
    int w = threadIdx.x >> 5, lane = threadIdx.x & 31, r = lane & 15;
    int bn = blockIdx.x * 8 + w;

    float p0 = phi[bn * 3 + 0], p1 = phi[bn * 3 + 1], p2 = phi[bn * 3 + 2];

    float Ar[16];
    const float4* g4 = (const float4*)gen;
    #pragma unroll
    for (int q = 0; q < 4; ++q) {
        float4 a = g4[(0 * 256 + r * 16) / 4 + q];
        float4 b = g4[(1 * 256 + r * 16) / 4 + q];
        float4 c = g4[(2 * 256 + r * 16) / 4 + q];
        Ar[4 * q + 0] = p0 * a.x + p1 * b.x + p2 * c.x;
        Ar[4 * q + 1] = p0 * a.y + p1 * b.y + p2 * c.y;
        Ar[4 * q + 2] = p0 * a.z + p1 * b.z + p2 * c.z;
        Ar[4 * q + 3] = p0 * a.w + p1 * b.w + p2 * c.w;
    }
    if (lane < 16) {
        float4* A4 = (float4*)(g_A + (size_t)bn * 256 + r * 16);
        #pragma unroll
        for (int q = 0; q < 4; ++q)
            A4[q] = make_float4(Ar[4*q], Ar[4*q+1], Ar[4*q+2], Ar[4*q+3]);
    }

    float nAr[16];
    #pragma unroll
    for (int c = 0; c < 16; ++c) nAr[c] = -Ar[c];

    float x_own = mu[bn * 16 + r];
    float v = exp_apply(nAr, x_own);
    if (lane < 16) g_V[bn * 16 + lane] = v;
}

// ---------------------------------------------------------------------------
// Kernel 2: warp-per-row main pass over the L2-resident beta_avg.
// Block = 8 warps = 8 rows of one batch. V[b] in smem stride-20: lane stride
// is 20 words -> banks {0,20,8,28,16,4,24,12} per 8-lane phase, conflict-free.
// j-indexing MUST stay lane + 32*jj (R7 lesson: 4*lane strides = 16-way conflicts).
// ---------------------------------------------------------------------------
__global__ __launch_bounds__(256)
void vffn_main_kernel(const float* __restrict__ mu,
                      const float* __restrict__ mu_prior,
                      const float* __restrict__ lr_ptr,
                      float* __restrict__ out) {
    __shared__ float Vs[N_ * 20];
    __shared__ float qs[N_];
    __shared__ float scratch[8][16];

    int t = threadIdx.x, lane = t & 31, w = t >> 5, r = lane & 15;
    int b = blockIdx.x >> 6;                 // 64 blocks per batch
    int i = ((blockIdx.x & 63) << 3) + w;    // this warp's row
    int bn = b * N_ + i;
    float lr = *lr_ptr;

    // Stage V[b] into padded smem (stride 20 floats; float4-aligned)
    const float4* V4 = (const float4*)(g_V + (size_t)b * N_ * K_);
    for (int idx = t; idx < N_ * 4; idx += 256) {
        int j = idx >> 2, q = idx & 3;
        ((float4*)(Vs + j * 20))[q] = V4[j * 4 + q];
    }
    __syncthreads();
    for (int j = t; j < N_; j += 256) {
        float q = 0.0f;
        #pragma unroll
        for (int k = 0; k < 16; ++k) { float v = Vs[j * 20 + k]; q += v * v; }
        qs[j] = q;
    }
    __syncthreads();

    float vi[16];
    #pragma unroll
    for (int q = 0; q < 4; ++q) {
        float4 v4 = ((const float4*)(Vs + i * 20))[q];
        vi[4*q] = v4.x; vi[4*q+1] = v4.y; vi[4*q+2] = v4.z; vi[4*q+3] = v4.w;
    }
    float qi = qs[i];

    float S0 = 0.0f, sac = 0.0f;
    float Sv[16], Tv[16];
    #pragma unroll
    for (int k = 0; k < 16; ++k) { Sv[k] = 0.0f; Tv[k] = 0.0f; }

    // Batch this row's 16 bavg loads up front (coalesced, L2-resident)
    const float* ba = g_bavg + (size_t)b * NN + (size_t)i * N_;
    float cbv[16];
    #pragma unroll
    for (int jj = 0; jj < 16; ++jj) cbv[jj] = __ldg(ba + lane + 32 * jj);

    #pragma unroll 4
    for (int jj = 0; jj < 16; ++jj) {
        int j = lane + 32 * jj;
        float cb = cbv[jj];

        float vj[16];
        #pragma unroll
        for (int q = 0; q < 4; ++q) {
            float4 u = ((const float4*)(Vs + j * 20))[q];
            vj[4*q] = u.x; vj[4*q+1] = u.y; vj[4*q+2] = u.z; vj[4*q+3] = u.w;
        }
        float d0 = 0.0f, d1 = 0.0f;
        #pragma unroll
        for (int k = 0; k < 16; k += 2) { d0 += vi[k]*vj[k]; d1 += vi[k+1]*vj[k+1]; }
        float kl  = 0.5f * (qi + qs[j]) - (d0 + d1);   // / TAU = 1
        float wgt = cb * kl;
        S0  += cb;
        sac += wgt;
        #pragma unroll
        for (int k = 0; k < 16; ++k) {
            Sv[k] += cb  * vj[k];
            Tv[k] += wgt * vj[k];
        }
    }

    // Butterfly all-reduce of the 34 partials across the warp
    #pragma unroll
    for (int off = 16; off > 0; off >>= 1) {
        S0  += __shfl_xor_sync(0xffffffffu, S0,  off);
        sac += __shfl_xor_sync(0xffffffffu, sac, off);
        #pragma unroll
        for (int k = 0; k < 16; ++k) {
            Sv[k] += __shfl_xor_sync(0xffffffffu, Sv[k], off);
            Tv[k] += __shfl_xor_sync(0xffffffffu, Tv[k], off);
        }
    }

    // rv (pre-rotation gradient), replicated in all lanes
    float rv[16];
    #pragma unroll
    for (int k = 0; k < 16; ++k) {
        float r1 = S0 * vi[k] - Sv[k];                                // grad1 (tau=1)
        float r2 = sac * (1.0f - S0) * vi[k] + sac * Sv[k] - Tv[k];   // grad2 (tau*kappa=1)
        rv[k] = r1 + r2;
    }
    if (lane == 0) {
        #pragma unroll
        for (int c = 0; c < 16; ++c) scratch[w][c] = rv[c];
    }
    __syncwarp();
    float rv_own = scratch[w][r];

    // Rotation grad = exp(A) rv
    float Ar[16];
    const float4* A4 = (const float4*)(g_A + (size_t)bn * 256 + r * 16);
    #pragma unroll
    for (int q = 0; q < 4; ++q) {
        float4 a = A4[q];
        Ar[4*q] = a.x; Ar[4*q+1] = a.y; Ar[4*q+2] = a.z; Ar[4*q+3] = a.w;
    }
    float grad = exp_apply(Ar, rv_own);

    if (lane < 16) {
        float m  = mu[bn * 16 + lane];
        float mp = mu_prior[bn * 16 + lane];
        out[bn * 16 + lane] = m - lr * (0.001f * (m - mp) + grad);
    }
}

// ---------------------------------------------------------------------------
extern "C" void kernel_launch(void* const* d_in, const int* in_sizes, int n_in,
                              void* d_out, int out_size) {
    const float* mu       = (const float*)d_in[0];
    const float* beta     = (const float*)d_in[1];
    const float* mu_prior = (const float*)d_in[2];
    const float* phi      = (const float*)d_in[3];
    const float* gen      = (const float*)d_in[4];
    const float* lr       = (const float*)d_in[5];
    float* out = (float*)d_out;

    havg_kernel<<<(B_ * NN / 4) / 256, 256>>>(beta);
    prep_kernel<<<BN / 8, 256>>>(mu, phi, gen);
    vffn_main_kernel<<<BN / 8, 256>>>(mu, mu_prior, lr, out);
}

// round 9
// speedup vs baseline: 2.0331x; 1.1033x over previous
#include <cuda_runtime.h>
#include <cuda_bf16.h>

#define B_  8
#define H_  8
#define N_  512
#define K_  16
#define BN  (B_*N_)          // 4096
#define NN  (N_*N_)          // 262144
#define M_TAYLOR 16

__device__ float g_A[BN * 256];     // per-(b,n) algebra element A, row-major 16x16
__device__ float g_V[BN * K_];      // v = exp(-A) mu
__device__ float g_bavg[B_ * NN];   // head-averaged beta (8 MB)

// ---------------------------------------------------------------------------
// Warp-collective: y = exp(A) x for a 16x16 A.
// Lane l owns row r = l&15 of A. x_own = component r of x.
// ---------------------------------------------------------------------------
__device__ __forceinline__ float exp_apply(const float Ar[16], float x_own) {
    float x[16], y[16];
    #pragma unroll
    for (int c = 0; c < 16; ++c) {
        x[c] = __shfl_sync(0xffffffffu, x_own, c);
        y[c] = x[c];
    }
    float y_own = x_own;
    #pragma unroll
    for (int k = M_TAYLOR; k >= 1; --k) {
        float z0 = 0.0f, z1 = 0.0f;
        #pragma unroll
        for (int c = 0; c < 16; c += 2) {
            z0 += Ar[c]     * y[c];
            z1 += Ar[c + 1] * y[c + 1];
        }
        float zk = (z0 + z1) * (1.0f / (float)k);
        y_own = x_own + zk;
        #pragma unroll
        for (int c = 0; c < 16; ++c)
            y[c] = x[c] + __shfl_sync(0xffffffffu, zk, c);
    }
    return y_own;
}

// ---------------------------------------------------------------------------
// Kernel 0 (fused): blocks [0,2048) stream the beta head-average;
// blocks [2048,2560) do the per-(b,n) prep (A matrix + v = exp(-A) mu).
// Independent data -> prep latency hides behind the 64 MB stream.
// ---------------------------------------------------------------------------
__global__ __launch_bounds__(256)
void fused_prep_kernel(const float* __restrict__ beta,
                       const float* __restrict__ mu,
                       const float* __restrict__ phi,
                       const float* __restrict__ gen) {
    if (blockIdx.x < 2048) {
        // ---- head-average stream ----
        int m4 = blockIdx.x * 256 + threadIdx.x;   // float4 index, B_*NN/4 total
        int b  = m4 >> 16;                          // / (NN/4 = 65536)
        int r4 = m4 & 65535;
        const float4* src = (const float4*)beta + (size_t)b * (H_ * NN / 4) + r4;

        float4 v0 = src[0 * (NN/4)], v1 = src[1 * (NN/4)];
        float4 v2 = src[2 * (NN/4)], v3 = src[3 * (NN/4)];
        float4 v4 = src[4 * (NN/4)], v5 = src[5 * (NN/4)];
        float4 v6 = src[6 * (NN/4)], v7 = src[7 * (NN/4)];

        float4 s;
        s.x = (((v0.x + v1.x) + (v2.x + v3.x)) + ((v4.x + v5.x) + (v6.x + v7.x))) * 0.125f;
        s.y = (((v0.y + v1.y) + (v2.y + v3.y)) + ((v4.y + v5.y) + (v6.y + v7.y))) * 0.125f;
        s.z = (((v0.z + v1.z) + (v2.z + v3.z)) + ((v4.z + v5.z) + (v6.z + v7.z))) * 0.125f;
        s.w = (((v0.w + v1.w) + (v2.w + v3.w)) + ((v4.w + v5.w) + (v6.w + v7.w))) * 0.125f;

        ((float4*)g_bavg)[m4] = s;
    } else {
        // ---- prep: A = phi.G, v = exp(-A) mu ----
        int bid  = blockIdx.x - 2048;
        int w = threadIdx.x >> 5, lane = threadIdx.x & 31, r = lane & 15;
        int bn = bid * 8 + w;

        float p0 = phi[bn * 3 + 0], p1 = phi[bn * 3 + 1], p2 = phi[bn * 3 + 2];

        float Ar[16];
        const float4* g4 = (const float4*)gen;
        #pragma unroll
        for (int q = 0; q < 4; ++q) {
            float4 a = g4[(0 * 256 + r * 16) / 4 + q];
            float4 b = g4[(1 * 256 + r * 16) / 4 + q];
            float4 c = g4[(2 * 256 + r * 16) / 4 + q];
            Ar[4 * q + 0] = p0 * a.x + p1 * b.x + p2 * c.x;
            Ar[4 * q + 1] = p0 * a.y + p1 * b.y + p2 * c.y;
            Ar[4 * q + 2] = p0 * a.z + p1 * b.z + p2 * c.z;
            Ar[4 * q + 3] = p0 * a.w + p1 * b.w + p2 * c.w;
        }
        if (lane < 16) {
            float4* A4 = (float4*)(g_A + (size_t)bn * 256 + r * 16);
            #pragma unroll
            for (int q = 0; q < 4; ++q)
                A4[q] = make_float4(Ar[4*q], Ar[4*q+1], Ar[4*q+2], Ar[4*q+3]);
        }

        float nAr[16];
        #pragma unroll
        for (int c = 0; c < 16; ++c) nAr[c] = -Ar[c];

        float x_own = mu[bn * 16 + r];
        float v = exp_apply(nAr, x_own);
        if (lane < 16) g_V[bn * 16 + lane] = v;
    }
}

// ---------------------------------------------------------------------------
// Kernel 1: warp-per-row main pass over the L2-resident beta_avg.
// Block = 8 warps = 8 rows of one batch. V[b] in smem stride-20 (conflict-free
// float4 LDS: lane banks {0,20,8,28,16,4,24,12}).
// bavg loads done INSIDE the unroll-4 loop (R8 lesson: 16 batched __ldg +
// unroll-4 spilled registers).
// ---------------------------------------------------------------------------
__global__ __launch_bounds__(256)
void vffn_main_kernel(const float* __restrict__ mu,
                      const float* __restrict__ mu_prior,
                      const float* __restrict__ lr_ptr,
                      float* __restrict__ out) {
    __shared__ float Vs[N_ * 20];
    __shared__ float qs[N_];
    __shared__ float scratch[8][16];

    int t = threadIdx.x, lane = t & 31, w = t >> 5, r = lane & 15;
    int b = blockIdx.x >> 6;                 // 64 blocks per batch
    int i = ((blockIdx.x & 63) << 3) + w;    // this warp's row
    int bn = b * N_ + i;
    float lr = *lr_ptr;

    // Stage V[b] into padded smem (stride 20 floats; float4-aligned)
    const float4* V4 = (const float4*)(g_V + (size_t)b * N_ * K_);
    for (int idx = t; idx < N_ * 4; idx += 256) {
        int j = idx >> 2, q = idx & 3;
        ((float4*)(Vs + j * 20))[q] = V4[j * 4 + q];
    }
    __syncthreads();
    for (int j = t; j < N_; j += 256) {
        float q = 0.0f;
        #pragma unroll
        for (int k = 0; k < 16; ++k) { float v = Vs[j * 20 + k]; q += v * v; }
        qs[j] = q;
    }
    __syncthreads();

    float vi[16];
    #pragma unroll
    for (int q = 0; q < 4; ++q) {
        float4 v4 = ((const float4*)(Vs + i * 20))[q];
        vi[4*q] = v4.x; vi[4*q+1] = v4.y; vi[4*q+2] = v4.z; vi[4*q+3] = v4.w;
    }
    float qi = qs[i];

    float S0 = 0.0f, sac = 0.0f;
    float Sv[16], Tv[16];
    #pragma unroll
    for (int k = 0; k < 16; ++k) { Sv[k] = 0.0f; Tv[k] = 0.0f; }

    const float* ba = g_bavg + (size_t)b * NN + (size_t)i * N_;

    #pragma unroll 4
    for (int jj = 0; jj < 16; ++jj) {
        int j = lane + 32 * jj;
        float cb = __ldg(ba + j);            // L2-hit, pipelined by unroll-4

        float vj[16];
        #pragma unroll
        for (int q = 0; q < 4; ++q) {
            float4 u = ((const float4*)(Vs + j * 20))[q];
            vj[4*q] = u.x; vj[4*q+1] = u.y; vj[4*q+2] = u.z; vj[4*q+3] = u.w;
        }
        float d0 = 0.0f, d1 = 0.0f;
        #pragma unroll
        for (int k = 0; k < 16; k += 2) { d0 += vi[k]*vj[k]; d1 += vi[k+1]*vj[k+1]; }
        float kl  = 0.5f * (qi + qs[j]) - (d0 + d1);   // / TAU = 1
        float wgt = cb * kl;
        S0  += cb;
        sac += wgt;
        #pragma unroll
        for (int k = 0; k < 16; ++k) {
            Sv[k] += cb  * vj[k];
            Tv[k] += wgt * vj[k];
        }
    }

    // Butterfly all-reduce of the 34 partials across the warp
    #pragma unroll
    for (int off = 16; off > 0; off >>= 1) {
        S0  += __shfl_xor_sync(0xffffffffu, S0,  off);
        sac += __shfl_xor_sync(0xffffffffu, sac, off);
        #pragma unroll
        for (int k = 0; k < 16; ++k) {
            Sv[k] += __shfl_xor_sync(0xffffffffu, Sv[k], off);
            Tv[k] += __shfl_xor_sync(0xffffffffu, Tv[k], off);
        }
    }

    // rv (pre-rotation gradient), replicated in all lanes
    float rv[16];
    #pragma unroll
    for (int k = 0; k < 16; ++k) {
        float r1 = S0 * vi[k] - Sv[k];                                // grad1 (tau=1)
        float r2 = sac * (1.0f - S0) * vi[k] + sac * Sv[k] - Tv[k];   // grad2 (tau*kappa=1)
        rv[k] = r1 + r2;
    }
    if (lane == 0) {
        #pragma unroll
        for (int c = 0; c < 16; ++c) scratch[w][c] = rv[c];
    }
    __syncwarp();
    float rv_own = scratch[w][r];

    // Rotation grad = exp(A) rv
    float Ar[16];
    const float4* A4 = (const float4*)(g_A + (size_t)bn * 256 + r * 16);
    #pragma unroll
    for (int q = 0; q < 4; ++q) {
        float4 a = A4[q];
        Ar[4*q] = a.x; Ar[4*q+1] = a.y; Ar[4*q+2] = a.z; Ar[4*q+3] = a.w;
    }
    float grad = exp_apply(Ar, rv_own);

    if (lane < 16) {
        float m  = mu[bn * 16 + lane];
        float mp = mu_prior[bn * 16 + lane];
        out[bn * 16 + lane] = m - lr * (0.001f * (m - mp) + grad);
    }
}

// ---------------------------------------------------------------------------
extern "C" void kernel_launch(void* const* d_in, const int* in_sizes, int n_in,
                              void* d_out, int out_size) {
    const float* mu       = (const float*)d_in[0];
    const float* beta     = (const float*)d_in[1];
    const float* mu_prior = (const float*)d_in[2];
    const float* phi      = (const float*)d_in[3];
    const float* gen      = (const float*)d_in[4];
    const float* lr       = (const float*)d_in[5];
    float* out = (float*)d_out;

    fused_prep_kernel<<<2048 + BN / 8, 256>>>(beta, mu, phi, gen);
    vffn_main_kernel<<<BN / 8, 256>>>(mu, mu_prior, lr, out);
}

// round 10
// speedup vs baseline: 2.1567x; 1.0608x over previous
#include <cuda_runtime.h>
#include <cuda_bf16.h>

#define B_  8
#define H_  8
#define N_  512
#define K_  16
#define BN  (B_*N_)          // 4096
#define NN  (N_*N_)          // 262144
#define M_TAYLOR 16

__device__ float g_A[BN * 256];     // per-(b,n) algebra element A, row-major 16x16
__device__ float g_V[BN * K_];      // v = exp(-A) mu
__device__ float g_bavg[B_ * NN];   // head-averaged beta (8 MB)

// ---------------------------------------------------------------------------
// Warp-collective: y = exp(A) x for a 16x16 A.
// Lane l owns row r = l&15 of A. x_own = component r of x.
// ---------------------------------------------------------------------------
__device__ __forceinline__ float exp_apply(const float Ar[16], float x_own) {
    float x[16], y[16];
    #pragma unroll
    for (int c = 0; c < 16; ++c) {
        x[c] = __shfl_sync(0xffffffffu, x_own, c);
        y[c] = x[c];
    }
    float y_own = x_own;
    #pragma unroll
    for (int k = M_TAYLOR; k >= 1; --k) {
        float z0 = 0.0f, z1 = 0.0f;
        #pragma unroll
        for (int c = 0; c < 16; c += 2) {
            z0 += Ar[c]     * y[c];
            z1 += Ar[c + 1] * y[c + 1];
        }
        float zk = (z0 + z1) * (1.0f / (float)k);
        y_own = x_own + zk;
        #pragma unroll
        for (int c = 0; c < 16; ++c)
            y[c] = x[c] + __shfl_sync(0xffffffffu, zk, c);
    }
    return y_own;
}

// ---------------------------------------------------------------------------
// Kernel 0 (fused): blocks [0,2048) stream the beta head-average;
// blocks [2048,2560) do the per-(b,n) prep (A matrix + v = exp(-A) mu).
// ---------------------------------------------------------------------------
__global__ __launch_bounds__(256)
void fused_prep_kernel(const float* __restrict__ beta,
                       const float* __restrict__ mu,
                       const float* __restrict__ phi,
                       const float* __restrict__ gen) {
    if (blockIdx.x < 2048) {
        int m4 = blockIdx.x * 256 + threadIdx.x;   // float4 index, B_*NN/4 total
        int b  = m4 >> 16;                          // / (NN/4 = 65536)
        int r4 = m4 & 65535;
        const float4* src = (const float4*)beta + (size_t)b * (H_ * NN / 4) + r4;

        float4 v0 = src[0 * (NN/4)], v1 = src[1 * (NN/4)];
        float4 v2 = src[2 * (NN/4)], v3 = src[3 * (NN/4)];
        float4 v4 = src[4 * (NN/4)], v5 = src[5 * (NN/4)];
        float4 v6 = src[6 * (NN/4)], v7 = src[7 * (NN/4)];

        float4 s;
        s.x = (((v0.x + v1.x) + (v2.x + v3.x)) + ((v4.x + v5.x) + (v6.x + v7.x))) * 0.125f;
        s.y = (((v0.y + v1.y) + (v2.y + v3.y)) + ((v4.y + v5.y) + (v6.y + v7.y))) * 0.125f;
        s.z = (((v0.z + v1.z) + (v2.z + v3.z)) + ((v4.z + v5.z) + (v6.z + v7.z))) * 0.125f;
        s.w = (((v0.w + v1.w) + (v2.w + v3.w)) + ((v4.w + v5.w) + (v6.w + v7.w))) * 0.125f;

        ((float4*)g_bavg)[m4] = s;
    } else {
        int bid  = blockIdx.x - 2048;
        int w = threadIdx.x >> 5, lane = threadIdx.x & 31, r = lane & 15;
        int bn = bid * 8 + w;

        float p0 = phi[bn * 3 + 0], p1 = phi[bn * 3 + 1], p2 = phi[bn * 3 + 2];

        float Ar[16];
        const float4* g4 = (const float4*)gen;
        #pragma unroll
        for (int q = 0; q < 4; ++q) {
            float4 a = g4[(0 * 256 + r * 16) / 4 + q];
            float4 b = g4[(1 * 256 + r * 16) / 4 + q];
            float4 c = g4[(2 * 256 + r * 16) / 4 + q];
            Ar[4 * q + 0] = p0 * a.x + p1 * b.x + p2 * c.x;
            Ar[4 * q + 1] = p0 * a.y + p1 * b.y + p2 * c.y;
            Ar[4 * q + 2] = p0 * a.z + p1 * b.z + p2 * c.z;
            Ar[4 * q + 3] = p0 * a.w + p1 * b.w + p2 * c.w;
        }
        if (lane < 16) {
            float4* A4 = (float4*)(g_A + (size_t)bn * 256 + r * 16);
            #pragma unroll
            for (int q = 0; q < 4; ++q)
                A4[q] = make_float4(Ar[4*q], Ar[4*q+1], Ar[4*q+2], Ar[4*q+3]);
        }

        float nAr[16];
        #pragma unroll
        for (int c = 0; c < 16; ++c) nAr[c] = -Ar[c];

        float x_own = mu[bn * 16 + r];
        float v = exp_apply(nAr, x_own);
        if (lane < 16) g_V[bn * 16 + lane] = v;
    }
}

// ---------------------------------------------------------------------------
// Kernel 1: warp-per-row main pass. Block = 8 warps = 8 rows of one batch.
// ALL global traffic staged into smem up front:
//   Vs  : V[b] stride-20 padded   (conflict-free float4 LDS)
//   cbs : this block's 8 bavg rows (16 KB, contiguous, coalesced float4)
// Inner loop is pure LDS+FMA -> no per-iteration LDG latency to hide.
// ---------------------------------------------------------------------------
__global__ __launch_bounds__(256)
void vffn_main_kernel(const float* __restrict__ mu,
                      const float* __restrict__ mu_prior,
                      const float* __restrict__ lr_ptr,
                      float* __restrict__ out) {
    __shared__ float Vs[N_ * 20];
    __shared__ float qs[N_];
    __shared__ float cbs[8 * N_];      // 8 rows x 512 cb values
    __shared__ float scratch[8][16];

    int t = threadIdx.x, lane = t & 31, w = t >> 5, r = lane & 15;
    int b = blockIdx.x >> 6;                 // 64 blocks per batch
    int i0 = (blockIdx.x & 63) << 3;
    int i = i0 + w;                          // this warp's row
    int bn = b * N_ + i;
    float lr = *lr_ptr;

    // Stage V[b] into padded smem (stride 20 floats; float4-aligned)
    const float4* V4 = (const float4*)(g_V + (size_t)b * N_ * K_);
    for (int idx = t; idx < N_ * 4; idx += 256) {
        int j = idx >> 2, q = idx & 3;
        ((float4*)(Vs + j * 20))[q] = V4[j * 4 + q];
    }
    // Stage this block's 8 bavg rows (contiguous 16 KB, coalesced float4)
    {
        const float4* ba4 = (const float4*)(g_bavg + (size_t)b * NN + (size_t)i0 * N_);
        float4* cb4 = (float4*)cbs;
        #pragma unroll
        for (int q = 0; q < 4; ++q)
            cb4[t + 256 * q] = ba4[t + 256 * q];
    }
    __syncthreads();
    for (int j = t; j < N_; j += 256) {
        float q = 0.0f;
        #pragma unroll
        for (int k = 0; k < 16; ++k) { float v = Vs[j * 20 + k]; q += v * v; }
        qs[j] = q;
    }
    __syncthreads();

    float vi[16];
    #pragma unroll
    for (int q = 0; q < 4; ++q) {
        float4 v4 = ((const float4*)(Vs + i * 20))[q];
        vi[4*q] = v4.x; vi[4*q+1] = v4.y; vi[4*q+2] = v4.z; vi[4*q+3] = v4.w;
    }
    float qi = qs[i];

    float S0 = 0.0f, sac = 0.0f;
    float Sv[16], Tv[16];
    #pragma unroll
    for (int k = 0; k < 16; ++k) { Sv[k] = 0.0f; Tv[k] = 0.0f; }

    const float* cbrow = cbs + w * N_;

    #pragma unroll 4
    for (int jj = 0; jj < 16; ++jj) {
        int j = lane + 32 * jj;
        float cb = cbrow[j];                 // lane-stride-1, conflict-free LDS

        float vj[16];
        #pragma unroll
        for (int q = 0; q < 4; ++q) {
            float4 u = ((const float4*)(Vs + j * 20))[q];
            vj[4*q] = u.x; vj[4*q+1] = u.y; vj[4*q+2] = u.z; vj[4*q+3] = u.w;
        }
        float d0 = 0.0f, d1 = 0.0f;
        #pragma unroll
        for (int k = 0; k < 16; k += 2) { d0 += vi[k]*vj[k]; d1 += vi[k+1]*vj[k+1]; }
        float kl  = 0.5f * (qi + qs[j]) - (d0 + d1);   // / TAU = 1
        float wgt = cb * kl;
        S0  += cb;
        sac += wgt;
        #pragma unroll
        for (int k = 0; k < 16; ++k) {
            Sv[k] += cb  * vj[k];
            Tv[k] += wgt * vj[k];
        }
    }

    // Butterfly all-reduce of the 34 partials across the warp
    #pragma unroll
    for (int off = 16; off > 0; off >>= 1) {
        S0  += __shfl_xor_sync(0xffffffffu, S0,  off);
        sac += __shfl_xor_sync(0xffffffffu, sac, off);
        #pragma unroll
        for (int k = 0; k < 16; ++k) {
            Sv[k] += __shfl_xor_sync(0xffffffffu, Sv[k], off);
            Tv[k] += __shfl_xor_sync(0xffffffffu, Tv[k], off);
        }
    }

    // rv (pre-rotation gradient), replicated in all lanes
    float rv[16];
    #pragma unroll
    for (int k = 0; k < 16; ++k) {
        float r1 = S0 * vi[k] - Sv[k];                                // grad1 (tau=1)
        float r2 = sac * (1.0f - S0) * vi[k] + sac * Sv[k] - Tv[k];   // grad2 (tau*kappa=1)
        rv[k] = r1 + r2;
    }
    if (lane == 0) {
        #pragma unroll
        for (int c = 0; c < 16; ++c) scratch[w][c] = rv[c];
    }
    __syncwarp();
    float rv_own = scratch[w][r];

    // Rotation grad = exp(A) rv
    float Ar[16];
    const float4* A4 = (const float4*)(g_A + (size_t)bn * 256 + r * 16);
    #pragma unroll
    for (int q = 0; q < 4; ++q) {
        float4 a = A4[q];
        Ar[4*q] = a.x; Ar[4*q+1] = a.y; Ar[4*q+2] = a.z; Ar[4*q+3] = a.w;
    }
    float grad = exp_apply(Ar, rv_own);

    if (lane < 16) {
        float m  = mu[bn * 16 + lane];
        float mp = mu_prior[bn * 16 + lane];
        out[bn * 16 + lane] = m - lr * (0.001f * (m - mp) + grad);
    }
}

// ---------------------------------------------------------------------------
extern "C" void kernel_launch(void* const* d_in, const int* in_sizes, int n_in,
                              void* d_out, int out_size) {
    const float* mu       = (const float*)d_in[0];
    const float* beta     = (const float*)d_in[1];
    const float* mu_prior = (const float*)d_in[2];
    const float* phi      = (const float*)d_in[3];
    const float* gen      = (const float*)d_in[4];
    const float* lr       = (const float*)d_in[5];
    float* out = (float*)d_out;

    fused_prep_kernel<<<2048 + BN / 8, 256>>>(beta, mu, phi, gen);
    vffn_main_kernel<<<BN / 8, 256>>>(mu, mu_prior, lr, out);
}

// round 11
// speedup vs baseline: 2.2817x; 1.0580x over previous
#include <cuda_runtime.h>
#include <cuda_bf16.h>

#define B_  8
#define H_  8
#define N_  512
#define K_  16
#define BN  (B_*N_)          // 4096
#define NN  (N_*N_)          // 262144

__device__ float g_A[BN * 256];     // per-(b,n) algebra element A, row-major 16x16
__device__ float g_V[BN * K_];      // v = exp(-A) mu
__device__ float g_bavg[B_ * NN];   // head-averaged beta (8 MB)

// ---------------------------------------------------------------------------
// Warp-collective: y = exp(A) x for a 16x16 A (M-term Taylor, Horner).
// Lane l owns row r = l&15 of A. x_own = component r of x (lanes 16-31 mirror).
// Returns component r of exp(A) x.
// ---------------------------------------------------------------------------
template<int M>
__device__ __forceinline__ float exp_apply(const float Ar[16], float x_own) {
    float x[16], y[16];
    #pragma unroll
    for (int c = 0; c < 16; ++c) {
        x[c] = __shfl_sync(0xffffffffu, x_own, c);
        y[c] = x[c];
    }
    float y_own = x_own;
    #pragma unroll
    for (int k = M; k >= 1; --k) {
        float z0 = 0.0f, z1 = 0.0f;
        #pragma unroll
        for (int c = 0; c < 16; c += 2) {
            z0 += Ar[c]     * y[c];
            z1 += Ar[c + 1] * y[c + 1];
        }
        float zk = (z0 + z1) * (1.0f / (float)k);
        y_own = x_own + zk;
        #pragma unroll
        for (int c = 0; c < 16; ++c)
            y[c] = x[c] + __shfl_sync(0xffffffffu, zk, c);
    }
    return y_own;
}

// ---------------------------------------------------------------------------
// Kernel 0 (fused): blocks [0,2048) stream the beta head-average;
// blocks [2048,2560) do the per-(b,n) prep (A matrix + v = exp(-A) mu).
// Prep latency hides behind the 64 MB DRAM stream (stream blocks issue at 8%).
// ---------------------------------------------------------------------------
__global__ __launch_bounds__(256)
void fused_prep_kernel(const float* __restrict__ beta,
                       const float* __restrict__ mu,
                       const float* __restrict__ phi,
                       const float* __restrict__ gen) {
    if (blockIdx.x < 2048) {
        int m4 = blockIdx.x * 256 + threadIdx.x;   // float4 index, B_*NN/4 total
        int b  = m4 >> 16;                          // / (NN/4 = 65536)
        int r4 = m4 & 65535;
        const float4* src = (const float4*)beta + (size_t)b * (H_ * NN / 4) + r4;

        float4 v0 = src[0 * (NN/4)], v1 = src[1 * (NN/4)];
        float4 v2 = src[2 * (NN/4)], v3 = src[3 * (NN/4)];
        float4 v4 = src[4 * (NN/4)], v5 = src[5 * (NN/4)];
        float4 v6 = src[6 * (NN/4)], v7 = src[7 * (NN/4)];

        float4 s;
        s.x = (((v0.x + v1.x) + (v2.x + v3.x)) + ((v4.x + v5.x) + (v6.x + v7.x))) * 0.125f;
        s.y = (((v0.y + v1.y) + (v2.y + v3.y)) + ((v4.y + v5.y) + (v6.y + v7.y))) * 0.125f;
        s.z = (((v0.z + v1.z) + (v2.z + v3.z)) + ((v4.z + v5.z) + (v6.z + v7.z))) * 0.125f;
        s.w = (((v0.w + v1.w) + (v2.w + v3.w)) + ((v4.w + v5.w) + (v6.w + v7.w))) * 0.125f;

        ((float4*)g_bavg)[m4] = s;
    } else {
        int bid  = blockIdx.x - 2048;
        int w = threadIdx.x >> 5, lane = threadIdx.x & 31, r = lane & 15;
        int bn = bid * 8 + w;

        float p0 = phi[bn * 3 + 0], p1 = phi[bn * 3 + 1], p2 = phi[bn * 3 + 2];

        float Ar[16];
        const float4* g4 = (const float4*)gen;
        #pragma unroll
        for (int q = 0; q < 4; ++q) {
            float4 a = g4[(0 * 256 + r * 16) / 4 + q];
            float4 b = g4[(1 * 256 + r * 16) / 4 + q];
            float4 c = g4[(2 * 256 + r * 16) / 4 + q];
            Ar[4 * q + 0] = p0 * a.x + p1 * b.x + p2 * c.x;
            Ar[4 * q + 1] = p0 * a.y + p1 * b.y + p2 * c.y;
            Ar[4 * q + 2] = p0 * a.z + p1 * b.z + p2 * c.z;
            Ar[4 * q + 3] = p0 * a.w + p1 * b.w + p2 * c.w;
        }
        if (lane < 16) {
            float4* A4 = (float4*)(g_A + (size_t)bn * 256 + r * 16);
            #pragma unroll
            for (int q = 0; q < 4; ++q)
                A4[q] = make_float4(Ar[4*q], Ar[4*q+1], Ar[4*q+2], Ar[4*q+3]);
        }

        float nAr[16];
        #pragma unroll
        for (int c = 0; c < 16; ++c) nAr[c] = -Ar[c];

        float x_own = mu[bn * 16 + r];
        float v = exp_apply<16>(nAr, x_own);
        if (lane < 16) g_V[bn * 16 + lane] = v;
    }
}

// ---------------------------------------------------------------------------
// Kernel 1: warp-per-row main pass. Block = 8 warps = 8 rows of one batch.
// Global traffic staged into smem up front (Vs stride-20 conflict-free; cbs
// contiguous). Epilogue uses recursive-halving reduce-scatter (31 SHFL) over
// packed [Sv|Tv] so lane l ends holding element l — feeding exp_apply's
// distributed input directly (no smem scratch, no 170-SHFL butterfly).
// ---------------------------------------------------------------------------
__global__ __launch_bounds__(256)
void vffn_main_kernel(const float* __restrict__ mu,
                      const float* __restrict__ mu_prior,
                      const float* __restrict__ lr_ptr,
                      float* __restrict__ out) {
    __shared__ float Vs[N_ * 20];
    __shared__ float qs[N_];
    __shared__ float cbs[8 * N_];      // 8 rows x 512 cb values

    int t = threadIdx.x, lane = t & 31, w = t >> 5, r = lane & 15;
    int b = blockIdx.x >> 6;                 // 64 blocks per batch
    int i0 = (blockIdx.x & 63) << 3;
    int i = i0 + w;                          // this warp's row
    int bn = b * N_ + i;
    float lr = *lr_ptr;

    // Stage V[b] into padded smem (stride 20 floats; float4-aligned)
    const float4* V4 = (const float4*)(g_V + (size_t)b * N_ * K_);
    for (int idx = t; idx < N_ * 4; idx += 256) {
        int j = idx >> 2, q = idx & 3;
        ((float4*)(Vs + j * 20))[q] = V4[j * 4 + q];
    }
    // Stage this block's 8 bavg rows (contiguous 16 KB, coalesced float4)
    {
        const float4* ba4 = (const float4*)(g_bavg + (size_t)b * NN + (size_t)i0 * N_);
        float4* cb4 = (float4*)cbs;
        #pragma unroll
        for (int q = 0; q < 4; ++q)
            cb4[t + 256 * q] = ba4[t + 256 * q];
    }
    __syncthreads();
    for (int j = t; j < N_; j += 256) {
        float q = 0.0f;
        #pragma unroll
        for (int k = 0; k < 16; ++k) { float v = Vs[j * 20 + k]; q += v * v; }
        qs[j] = q;
    }
    __syncthreads();

    float vi[16];
    #pragma unroll
    for (int q = 0; q < 4; ++q) {
        float4 v4 = ((const float4*)(Vs + i * 20))[q];
        vi[4*q] = v4.x; vi[4*q+1] = v4.y; vi[4*q+2] = v4.z; vi[4*q+3] = v4.w;
    }
    float qi = qs[i];

    float S0 = 0.0f, sac = 0.0f;
    float u[32];                          // u[0..15]=Sv, u[16..31]=Tv
    #pragma unroll
    for (int k = 0; k < 32; ++k) u[k] = 0.0f;

    const float* cbrow = cbs + w * N_;

    #pragma unroll 4
    for (int jj = 0; jj < 16; ++jj) {
        int j = lane + 32 * jj;
        float cb = cbrow[j];                 // lane-stride-1, conflict-free LDS

        float vj[16];
        #pragma unroll
        for (int q = 0; q < 4; ++q) {
            float4 uu = ((const float4*)(Vs + j * 20))[q];
            vj[4*q] = uu.x; vj[4*q+1] = uu.y; vj[4*q+2] = uu.z; vj[4*q+3] = uu.w;
        }
        float d0 = 0.0f, d1 = 0.0f;
        #pragma unroll
        for (int k = 0; k < 16; k += 2) { d0 += vi[k]*vj[k]; d1 += vi[k+1]*vj[k+1]; }
        float kl  = 0.5f * (qi + qs[j]) - (d0 + d1);   // / TAU = 1
        float wgt = cb * kl;
        S0  += cb;
        sac += wgt;
        #pragma unroll
        for (int k = 0; k < 16; ++k) {
            u[k]      += cb  * vj[k];
            u[16 + k] += wgt * vj[k];
        }
    }

    // ---- recursive-halving reduce-scatter of u[32]: 31 SHFL total.
    // After the cascade, lane l holds sum-over-lanes of original u[l].
    {
        bool hi = (lane & 16) != 0;
        #pragma unroll
        for (int k = 0; k < 16; ++k) {
            float send = hi ? u[k] : u[k + 16];
            float keep = hi ? u[k + 16] : u[k];
            u[k] = keep + __shfl_xor_sync(0xffffffffu, send, 16);
        }
        hi = (lane & 8) != 0;
        #pragma unroll
        for (int k = 0; k < 8; ++k) {
            float send = hi ? u[k] : u[k + 8];
            float keep = hi ? u[k + 8] : u[k];
            u[k] = keep + __shfl_xor_sync(0xffffffffu, send, 8);
        }
        hi = (lane & 4) != 0;
        #pragma unroll
        for (int k = 0; k < 4; ++k) {
            float send = hi ? u[k] : u[k + 4];
            float keep = hi ? u[k + 4] : u[k];
            u[k] = keep + __shfl_xor_sync(0xffffffffu, send, 4);
        }
        hi = (lane & 2) != 0;
        #pragma unroll
        for (int k = 0; k < 2; ++k) {
            float send = hi ? u[k] : u[k + 2];
            float keep = hi ? u[k + 2] : u[k];
            u[k] = keep + __shfl_xor_sync(0xffffffffu, send, 2);
        }
        hi = (lane & 1) != 0;
        {
            float send = hi ? u[0] : u[1];
            float keep = hi ? u[1] : u[0];
            u[0] = keep + __shfl_xor_sync(0xffffffffu, send, 1);
        }
    }
    // lane l (<16): u[0] = Sv[l]; lane l (>=16): u[0] = Tv[l-16]. Swap halves:
    float other = __shfl_xor_sync(0xffffffffu, u[0], 16);
    float Sv_f = (lane < 16) ? u[0] : other;
    float Tv_f = (lane < 16) ? other : u[0];

    // S0 / sac full butterfly (10 SHFL)
    #pragma unroll
    for (int off = 16; off > 0; off >>= 1) {
        S0  += __shfl_xor_sync(0xffffffffu, S0,  off);
        sac += __shfl_xor_sync(0xffffffffu, sac, off);
    }

    // rv component r, naturally distributed (lane r holds rv[r])
    float vik = vi[r];
    float rv_own = (S0 * vik - Sv_f)
                 + (sac * (1.0f - S0) * vik + sac * Sv_f - Tv_f);

    // Rotation grad = exp(A) rv
    float Ar[16];
    const float4* A4 = (const float4*)(g_A + (size_t)bn * 256 + r * 16);
    #pragma unroll
    for (int q = 0; q < 4; ++q) {
        float4 a = A4[q];
        Ar[4*q] = a.x; Ar[4*q+1] = a.y; Ar[4*q+2] = a.z; Ar[4*q+3] = a.w;
    }
    float grad = exp_apply<8>(Ar, rv_own);

    if (lane < 16) {
        float m  = mu[bn * 16 + lane];
        float mp = mu_prior[bn * 16 + lane];
        out[bn * 16 + lane] = m - lr * (0.001f * (m - mp) + grad);
    }
}

// ---------------------------------------------------------------------------
extern "C" void kernel_launch(void* const* d_in, const int* in_sizes, int n_in,
                              void* d_out, int out_size) {
    const float* mu       = (const float*)d_in[0];
    const float* beta     = (const float*)d_in[1];
    const float* mu_prior = (const float*)d_in[2];
    const float* phi      = (const float*)d_in[3];
    const float* gen      = (const float*)d_in[4];
    const float* lr       = (const float*)d_in[5];
    float* out = (float*)d_out;

    fused_prep_kernel<<<2048 + BN / 8, 256>>>(beta, mu, phi, gen);
    vffn_main_kernel<<<BN / 8, 256>>>(mu, mu_prior, lr, out);
}